// round 13
// baseline (speedup 1.0000x reference)
#include <cuda_runtime.h>
#include <cuda_fp16.h>
#include <math.h>
#include <cstdint>

// Problem constants (grid_hw fixed 64x64 for all 8 images)
#define N_TOK   32768
#define EMBED   1024
#define K1      588
#define K1P     592        // fp16 row stride, 16B-aligned, zero-padded
#define LLM     2048
#define M2      8192
#define K2      4096

// Scratch (device globals — no allocation allowed)
__device__ __half g_peh[(size_t)N_TOK * EMBED];    // gelu(patch GEMM), fp16
__device__ __half g_pxh[(size_t)N_TOK * K1P];      // fp16 pixels, padded rows
__device__ __half g_w1h[(size_t)EMBED * K1P];      // fp16 patch_w, padded rows
__device__ __half g_w2h[(size_t)LLM * K2];         // fp16 dense_w
__device__ __half g_A2h[(size_t)M2 * K2];          // fp16 rope'd merge-layout A2

// GEMM tiling: CTA 128x128, 8 warps of 64x32, K-chunk 64 halves, 2 CTAs/SM
// 3-stage cp.async ring, one __syncthreads per K-iter.
#define BM 128
#define BN 128
#define BK 64
#define SJH 72                 // smem row stride in halves (64+8)
#define STAGE_H ((BM + BN) * SJH)      // halves per stage
#define NSTAGE 3

__device__ __forceinline__ float gelu_exact(float x) {
    return 0.5f * x * (1.0f + erff(x * 0.70710678118654752f));
}
__device__ __forceinline__ void cp_async16(void* smem_dst, const void* gsrc, int src_bytes) {
    unsigned s = (unsigned)__cvta_generic_to_shared(smem_dst);
    asm volatile("cp.async.cg.shared.global [%0], [%1], 16, %2;\n" :: "r"(s), "l"(gsrc), "r"(src_bytes));
}
__device__ __forceinline__ void cp_commit() { asm volatile("cp.async.commit_group;\n"); }
__device__ __forceinline__ void cp_wait1()  { asm volatile("cp.async.wait_group 1;\n"); }

__device__ __forceinline__ void ldmx4(unsigned* r, unsigned saddr) {
    asm volatile("ldmatrix.sync.aligned.m8n8.x4.shared.b16 {%0,%1,%2,%3}, [%4];"
        : "=r"(r[0]), "=r"(r[1]), "=r"(r[2]), "=r"(r[3]) : "r"(saddr));
}
__device__ __forceinline__ void mma_f16(float* d, const unsigned* a, const unsigned* b) {
    asm volatile(
        "mma.sync.aligned.m16n8k16.row.col.f32.f16.f16.f32 "
        "{%0,%1,%2,%3}, {%4,%5,%6,%7}, {%8,%9}, {%0,%1,%2,%3};"
        : "+f"(d[0]), "+f"(d[1]), "+f"(d[2]), "+f"(d[3])
        : "r"(a[0]), "r"(a[1]), "r"(a[2]), "r"(a[3]), "r"(b[0]), "r"(b[1]));
}

// C[M,N] = A[M,K]*B[N,K]^T + bias (+GELU). A,B fp16 K-major.
// OutT = __half or float. M%128==0, N%128==0, K%8==0 (tail zero-filled).
template<int DO_GELU, typename OutT>
__global__ __launch_bounds__(256, 2) void hgemm_nt(
    const __half* __restrict__ A, const __half* __restrict__ B,
    const float* __restrict__ bias, OutT* __restrict__ C,
    int M, int N, int K)
{
    extern __shared__ __half smem[];

    const int tid  = threadIdx.x;
    const int lane = tid & 31;
    const int wid  = tid >> 5;
    const int m_w  = (wid >> 2) * 64;        // warp row offset (0,64)
    const int n_w  = (wid & 3) * 32;         // warp col offset (0,32,64,96)
    const int g    = lane >> 2;              // 0..7
    const int tg   = lane & 3;               // 0..3

    const int m0 = blockIdx.y * BM;
    const int n0 = blockIdx.x * BN;

    const unsigned sm_u = (unsigned)__cvta_generic_to_shared(smem);
    const int lr8   = lane & 7;
    const int lsel1 = (lane >> 3) & 1;
    const int lsel2 = (lane >> 4) & 1;
    unsigned aoff[4], boff[2];
    #pragma unroll
    for (int mt = 0; mt < 4; mt++)
        aoff[mt] = ((m_w + mt * 16 + lr8 + lsel1 * 8) * SJH + lsel2 * 8) * 2u;
    #pragma unroll
    for (int p = 0; p < 2; p++)
        boff[p]  = ((BM + n_w + p * 16 + lr8 + lsel2 * 8) * SJH + lsel1 * 8) * 2u;

    float acc[4][4][4];
    #pragma unroll
    for (int i = 0; i < 4; i++)
        #pragma unroll
        for (int j = 0; j < 4; j++)
            #pragma unroll
            for (int r = 0; r < 4; r++) acc[i][j][r] = 0.0f;

    const int nKT = (K + BK - 1) / BK;

    auto issue = [&](int t) {
        __half* base = smem + (t % NSTAGE) * STAGE_H;
        const int k0 = t * BK;
        #pragma unroll
        for (int i = 0; i < 4; i++) {          // A: 128 rows * 8 chunks(8h)
            const int idx = tid + i * 256;
            const int r = idx >> 3, c = idx & 7;
            const int kc = k0 + c * 8;
            const int bytes = (kc < K) ? 16 : 0;
            const int ks = (kc < K) ? kc : 0;
            cp_async16(base + r * SJH + c * 8, A + (size_t)(m0 + r) * K + ks, bytes);
        }
        #pragma unroll
        for (int i = 0; i < 4; i++) {          // B: 128 rows * 8 chunks
            const int idx = tid + i * 256;
            const int r = idx >> 3, c = idx & 7;
            const int kc = k0 + c * 8;
            const int bytes = (kc < K) ? 16 : 0;
            const int ks = (kc < K) ? kc : 0;
            cp_async16(base + (BM + r) * SJH + c * 8, B + (size_t)(n0 + r) * K + ks, bytes);
        }
    };

    issue(0); cp_commit();
    if (nKT > 1) issue(1);
    cp_commit();

    for (int kt = 0; kt < nKT; kt++) {
        cp_wait1();                 // tile kt resident (groups complete in order)
        __syncthreads();            // all warps done with MMA(kt-1); buffers safe
        if (kt + 2 < nKT) issue(kt + 2);
        cp_commit();                // one group per iter (possibly empty)

        const unsigned base = sm_u + (unsigned)(kt % NSTAGE) * STAGE_H * 2u;

        #pragma unroll
        for (int kk = 0; kk < BK; kk += 16) {
            unsigned afr[4][4];
            unsigned bfr[2][4];     // {b0,b1 of nt=2p; b0,b1 of nt=2p+1}
            #pragma unroll
            for (int mt = 0; mt < 4; mt++)
                ldmx4(afr[mt], base + aoff[mt] + kk * 2u);
            #pragma unroll
            for (int p = 0; p < 2; p++)
                ldmx4(bfr[p], base + boff[p] + kk * 2u);
            #pragma unroll
            for (int mt = 0; mt < 4; mt++) {
                #pragma unroll
                for (int nt = 0; nt < 4; nt++)
                    mma_f16(acc[mt][nt], afr[mt], &bfr[nt >> 1][(nt & 1) * 2]);
            }
        }
    }

    // Epilogue (registers only; no smem reuse, no barrier needed)
    #pragma unroll
    for (int mt = 0; mt < 4; mt++) {
        const int r0 = m0 + m_w + mt * 16 + g;
        #pragma unroll
        for (int nt = 0; nt < 4; nt++) {
            const int col = n0 + n_w + nt * 8 + tg * 2;
            const float b0 = bias[col], b1 = bias[col + 1];
            float v0 = acc[mt][nt][0] + b0;
            float v1 = acc[mt][nt][1] + b1;
            float v2 = acc[mt][nt][2] + b0;
            float v3 = acc[mt][nt][3] + b1;
            if (DO_GELU) {
                v0 = gelu_exact(v0); v1 = gelu_exact(v1);
                v2 = gelu_exact(v2); v3 = gelu_exact(v3);
            }
            if constexpr (sizeof(OutT) == 2) {
                *reinterpret_cast<__half2*>((__half*)C + (size_t)r0 * N + col)
                    = __floats2half2_rn(v0, v1);
                *reinterpret_cast<__half2*>((__half*)C + (size_t)(r0 + 8) * N + col)
                    = __floats2half2_rn(v2, v3);
            } else {
                *reinterpret_cast<float2*>((float*)C + (size_t)r0 * N + col)
                    = make_float2(v0, v1);
                *reinterpret_cast<float2*>((float*)C + (size_t)(r0 + 8) * N + col)
                    = make_float2(v2, v3);
            }
        }
    }
}

// ---------------- fp32 -> fp16 conversion with optional row padding ----------------
__global__ __launch_bounds__(256) void cvt_f16_pad(
    const float* __restrict__ in, __half* __restrict__ out,
    int kin, int kout, int ncr, int total)
{
    const int idx = blockIdx.x * 256 + threadIdx.x;
    if (idx >= total) return;
    const int r = idx / ncr, c = idx % ncr;
    const float* src = in + (size_t)r * kin + c * 8;
    int valid = kin - c * 8; if (valid > 8) valid = 8;
    __half h[8];
    #pragma unroll
    for (int i = 0; i < 8; i++)
        h[i] = (i < valid) ? __float2half_rn(src[i]) : __ushort_as_half((unsigned short)0);
    *reinterpret_cast<uint4*>(out + (size_t)r * kout + c * 8) = *reinterpret_cast<const uint4*>(h);
}

// ---------------- 2D RoPE + merge transpose, fp16 in/out, fully coalesced ----------------
// One warp per output row m. Thread handles 4-dim chunk j of each of the
// 4 source tokens (fp16 read, fp32 math), writes 32 B contiguous fp16.
__global__ __launch_bounds__(256) void rope_merge(
    const __half* __restrict__ pe,
    const float* __restrict__ cosx, const float* __restrict__ sinx,
    const float* __restrict__ cosy, const float* __restrict__ siny,
    __half* __restrict__ A2)
{
    const int wid  = threadIdx.x >> 5;
    const int lane = threadIdx.x & 31;
    const int m = blockIdx.x * 8 + wid;          // 0..8191
    const int b = m >> 10;
    const int rem = m & 1023;
    const int Y = rem >> 5, X = rem & 31;
    const int y0 = 2 * Y, x0 = 2 * X;

    const __half* rows[4];
    #pragma unroll
    for (int p = 0; p < 2; p++)
        #pragma unroll
        for (int q = 0; q < 2; q++)
            rows[p * 2 + q] = pe + ((size_t)(b * 4096 + (y0 + p) * 64 + (x0 + q))) * EMBED;

    __half* dst = A2 + (size_t)m * K2;

    #pragma unroll
    for (int it = 0; it < 8; it++) {
        const int j = it * 32 + lane;            // 4-dim chunk 0..255 (dims 4j..4j+3)
        const bool h1 = (j >= 128);              // second half: y-rope
        const int i0 = h1 ? (2 * j - 256) : (2 * j);
        const float* ct = h1 ? cosy : cosx;
        const float* st = h1 ? siny : sinx;

        __half hv[16];                           // index d*4 + pq
        #pragma unroll
        for (int p = 0; p < 2; p++) {
            #pragma unroll
            for (int q = 0; q < 2; q++) {
                const int pos = h1 ? (y0 + p) : (x0 + q);
                const float c0 = ct[pos * 256 + i0],     s0 = st[pos * 256 + i0];
                const float c1 = ct[pos * 256 + i0 + 1], s1 = st[pos * 256 + i0 + 1];
                const uint2 raw = reinterpret_cast<const uint2*>(rows[p * 2 + q])[j];
                const float2 v01 = __half22float2(*reinterpret_cast<const __half2*>(&raw.x));
                const float2 v23 = __half22float2(*reinterpret_cast<const __half2*>(&raw.y));
                const int pq = p * 2 + q;
                hv[0 * 4 + pq] = __float2half_rn(v01.x * c0 - v01.y * s0);
                hv[1 * 4 + pq] = __float2half_rn(v01.x * s0 + v01.y * c0);
                hv[2 * 4 + pq] = __float2half_rn(v23.x * c1 - v23.y * s1);
                hv[3 * 4 + pq] = __float2half_rn(v23.x * s1 + v23.y * c1);
            }
        }
        // dst column e*4 + pq, e = 4j+d  → contiguous 16 halves at 16j
        uint4* d16 = reinterpret_cast<uint4*>(dst + 16 * j);
        d16[0] = reinterpret_cast<const uint4*>(hv)[0];
        d16[1] = reinterpret_cast<const uint4*>(hv)[1];
    }
}

// ---------------- launch ----------------
extern "C" void kernel_launch(void* const* d_in, const int* in_sizes, int n_in,
                              void* d_out, int out_size)
{
    const float* px = (const float*)d_in[0];   // pixel_values [32768, 588]
    const float* pw = (const float*)d_in[2];   // patch_w [1024, 588]
    const float* pb = (const float*)d_in[3];   // patch_b [1024]
    const float* dw = (const float*)d_in[4];   // dense_w [2048, 4096]
    const float* db = (const float*)d_in[5];   // dense_b [2048]
    const float* cx = (const float*)d_in[6];
    const float* sx = (const float*)d_in[7];
    const float* cy = (const float*)d_in[8];
    const float* sy = (const float*)d_in[9];
    float* out = (float*)d_out;                // [8192, 2048]

    __half *peh, *pxh, *w1h, *w2h, *A2h;
    cudaGetSymbolAddress((void**)&peh, g_peh);
    cudaGetSymbolAddress((void**)&pxh, g_pxh);
    cudaGetSymbolAddress((void**)&w1h, g_w1h);
    cudaGetSymbolAddress((void**)&w2h, g_w2h);
    cudaGetSymbolAddress((void**)&A2h, g_A2h);

    const int SMEM = NSTAGE * STAGE_H * sizeof(__half);  // 110592 bytes
    cudaFuncSetAttribute((const void*)hgemm_nt<1, __half>,
                         cudaFuncAttributeMaxDynamicSharedMemorySize, SMEM);
    cudaFuncSetAttribute((const void*)hgemm_nt<0, float>,
                         cudaFuncAttributeMaxDynamicSharedMemorySize, SMEM);

    // Convert operands to fp16 (pixel & patch_w rows padded 588 -> 592)
    {
        int total = N_TOK * (K1P / 8);
        cvt_f16_pad<<<(total + 255) / 256, 256>>>(px, pxh, K1, K1P, K1P / 8, total);
        total = EMBED * (K1P / 8);
        cvt_f16_pad<<<(total + 255) / 256, 256>>>(pw, w1h, K1, K1P, K1P / 8, total);
        total = LLM * (K2 / 8);
        cvt_f16_pad<<<(total + 255) / 256, 256>>>(dw, w2h, K2, K2, K2 / 8, total);
    }

    // Stage 1: pe_h = fp16( gelu(px_h @ pw_h^T + pb) )
    {
        dim3 grid(EMBED / BN, N_TOK / BM);     // (8, 256)
        hgemm_nt<1, __half><<<grid, 256, SMEM>>>(pxh, w1h, pb, peh, N_TOK, EMBED, K1P);
    }

    // Stage 2: RoPE + merge transpose (fp32 math, fp16 io) into A2h
    rope_merge<<<M2 / 8, 256>>>(peh, cx, sx, cy, sy, A2h);

    // Stage 3: out = A2_h @ dw_h^T + db
    {
        dim3 grid(LLM / BN, M2 / BM);          // (16, 64)
        hgemm_nt<0, float><<<grid, 256, SMEM>>>(A2h, w2h, db, out, M2, LLM, K2);
    }
}

// round 14
// speedup vs baseline: 1.0125x; 1.0125x over previous
#include <cuda_runtime.h>
#include <cuda_fp16.h>
#include <math.h>
#include <cstdint>

// Problem constants (grid_hw fixed 64x64 for all 8 images)
#define N_TOK   32768
#define EMBED   1024
#define K1      588
#define K1P     592        // fp16 row stride, 16B-aligned, zero-padded
#define LLM     2048
#define M2      8192
#define K2      4096

// Scratch (device globals — no allocation allowed)
__device__ __half g_peh[(size_t)N_TOK * EMBED];    // gelu(patch GEMM), fp16
__device__ __half g_pxh[(size_t)N_TOK * K1P];      // fp16 pixels, padded rows
__device__ __half g_w1h[(size_t)EMBED * K1P];      // fp16 patch_w, padded rows
__device__ __half g_w2h[(size_t)LLM * K2];         // fp16 dense_w
__device__ __half g_A2h[(size_t)M2 * K2];          // fp16 rope'd merge-layout A2

// GEMM tiling: CTA 128x128, 8 warps of 64x32, K-chunk 64 halves, 2 CTAs/SM
#define BM 128
#define BN 128
#define BK 64
#define SJH 72                 // smem row stride in halves (64+8)
#define STAGE_H ((BM + BN) * SJH)
#define NSTAGE 3

__device__ __forceinline__ float gelu_exact(float x) {
    return 0.5f * x * (1.0f + erff(x * 0.70710678118654752f));
}
__device__ __forceinline__ void cp_async16(unsigned smem_dst, const void* gsrc, int src_bytes) {
    asm volatile("cp.async.cg.shared.global [%0], [%1], 16, %2;\n"
                 :: "r"(smem_dst), "l"(gsrc), "r"(src_bytes));
}
__device__ __forceinline__ void cp_commit() { asm volatile("cp.async.commit_group;\n"); }
__device__ __forceinline__ void cp_wait1()  { asm volatile("cp.async.wait_group 1;\n"); }

__device__ __forceinline__ void ldmx4(unsigned* r, unsigned saddr) {
    asm volatile("ldmatrix.sync.aligned.m8n8.x4.shared.b16 {%0,%1,%2,%3}, [%4];"
        : "=r"(r[0]), "=r"(r[1]), "=r"(r[2]), "=r"(r[3]) : "r"(saddr));
}
__device__ __forceinline__ void mma_f16(float* d, const unsigned* a, const unsigned* b) {
    asm volatile(
        "mma.sync.aligned.m16n8k16.row.col.f32.f16.f16.f32 "
        "{%0,%1,%2,%3}, {%4,%5,%6,%7}, {%8,%9}, {%0,%1,%2,%3};"
        : "+f"(d[0]), "+f"(d[1]), "+f"(d[2]), "+f"(d[3])
        : "r"(a[0]), "r"(a[1]), "r"(a[2]), "r"(a[3]), "r"(b[0]), "r"(b[1]));
}

// C[M,N] = A[M,K]*B[N,K]^T + bias (+GELU). A,B fp16 K-major.
// OutT = __half or float. M%128==0, N%128==0, K%8==0 (tail zero-filled).
template<int DO_GELU, typename OutT>
__global__ __launch_bounds__(256, 2) void hgemm_nt(
    const __half* __restrict__ A, const __half* __restrict__ B,
    const float* __restrict__ bias, OutT* __restrict__ C,
    int M, int N, int K)
{
    extern __shared__ __half smem[];

    const int tid  = threadIdx.x;
    const int lane = tid & 31;
    const int wid  = tid >> 5;
    const int m_w  = (wid >> 2) * 64;
    const int n_w  = (wid & 3) * 32;
    const int g    = lane >> 2;
    const int tg   = lane & 3;

    const int m0 = blockIdx.y * BM;
    const int n0 = blockIdx.x * BN;

    const unsigned sm_u = (unsigned)__cvta_generic_to_shared(smem);
    const int lr8   = lane & 7;
    const int lsel1 = (lane >> 3) & 1;
    const int lsel2 = (lane >> 4) & 1;
    unsigned aoff[4], boff[2];
    #pragma unroll
    for (int mt = 0; mt < 4; mt++)
        aoff[mt] = ((m_w + mt * 16 + lr8 + lsel1 * 8) * SJH + lsel2 * 8) * 2u;
    #pragma unroll
    for (int p = 0; p < 2; p++)
        boff[p]  = ((BM + n_w + p * 16 + lr8 + lsel2 * 8) * SJH + lsel1 * 8) * 2u;

    // ---- loader state: 2 global base pointers + 2 smem base offsets ----
    const int lr = tid >> 3;               // 0..31
    const int lc = tid & 7;                // 0..7 (8-half chunk)
    const __half* gA = A + (size_t)(m0 + lr) * K + lc * 8;
    const __half* gB = B + (size_t)(n0 + lr) * K + lc * 8;
    const size_t K32 = (size_t)K * 32;     // 32-row stride in elements
    const unsigned dA0 = (unsigned)(lr * SJH + lc * 8) * 2u;
    const unsigned dB0 = dA0 + (unsigned)(BM * SJH) * 2u;

    float acc[4][4][4];
    #pragma unroll
    for (int i = 0; i < 4; i++)
        #pragma unroll
        for (int j = 0; j < 4; j++)
            #pragma unroll
            for (int r = 0; r < 4; r++) acc[i][j][r] = 0.0f;

    const int nKT = (K + BK - 1) / BK;

    // full-tile load: no bounds math, pure pointer arithmetic
    auto issue_full = [&](int st) {
        const unsigned base = sm_u + (unsigned)st * (STAGE_H * 2);
        #pragma unroll
        for (int i = 0; i < 4; i++)
            cp_async16(base + dA0 + i * (32 * SJH * 2), gA + (size_t)i * K32, 16);
        #pragma unroll
        for (int i = 0; i < 4; i++)
            cp_async16(base + dB0 + i * (32 * SJH * 2), gB + (size_t)i * K32, 16);
        gA += BK; gB += BK;
    };
    // last-tile (partial) load: masked, zero-fills dst
    auto issue_last = [&](int st, int t) {
        const unsigned base = sm_u + (unsigned)st * (STAGE_H * 2);
        const int kc = t * BK + lc * 8;
        const int by = (kc + 8 <= K) ? 16 : 0;
        const __half* sa = by ? gA : A;
        const __half* sb = by ? gB : B;
        #pragma unroll
        for (int i = 0; i < 4; i++)
            cp_async16(base + dA0 + i * (32 * SJH * 2), sa + (size_t)i * K32, by);
        #pragma unroll
        for (int i = 0; i < 4; i++)
            cp_async16(base + dB0 + i * (32 * SJH * 2), sb + (size_t)i * K32, by);
        gA += BK; gB += BK;
    };
    auto issue_any = [&](int st, int t) {
        if ((t + 1) * BK <= K) issue_full(st); else issue_last(st, t);
    };

    issue_any(0, 0); cp_commit();
    if (nKT > 1) issue_any(1, 1);
    cp_commit();

    int st_mma = 0;
    int st_ld  = 2;
    for (int kt = 0; kt < nKT; kt++) {
        cp_wait1();
        __syncthreads();
        if (kt + 2 < nKT) issue_any(st_ld, kt + 2);
        cp_commit();

        const unsigned base = sm_u + (unsigned)st_mma * (STAGE_H * 2);

        #pragma unroll
        for (int kk = 0; kk < BK; kk += 16) {
            unsigned afr[4][4];
            unsigned bfr[2][4];
            #pragma unroll
            for (int mt = 0; mt < 4; mt++)
                ldmx4(afr[mt], base + aoff[mt] + kk * 2u);
            #pragma unroll
            for (int p = 0; p < 2; p++)
                ldmx4(bfr[p], base + boff[p] + kk * 2u);
            #pragma unroll
            for (int mt = 0; mt < 4; mt++) {
                #pragma unroll
                for (int nt = 0; nt < 4; nt++)
                    mma_f16(acc[mt][nt], afr[mt], &bfr[nt >> 1][(nt & 1) * 2]);
            }
        }
        st_mma = (st_mma == 2) ? 0 : st_mma + 1;
        st_ld  = (st_ld  == 2) ? 0 : st_ld  + 1;
    }

    // Epilogue (registers only)
    #pragma unroll
    for (int mt = 0; mt < 4; mt++) {
        const int r0 = m0 + m_w + mt * 16 + g;
        #pragma unroll
        for (int nt = 0; nt < 4; nt++) {
            const int col = n0 + n_w + nt * 8 + tg * 2;
            const float b0 = bias[col], b1 = bias[col + 1];
            float v0 = acc[mt][nt][0] + b0;
            float v1 = acc[mt][nt][1] + b1;
            float v2 = acc[mt][nt][2] + b0;
            float v3 = acc[mt][nt][3] + b1;
            if (DO_GELU) {
                v0 = gelu_exact(v0); v1 = gelu_exact(v1);
                v2 = gelu_exact(v2); v3 = gelu_exact(v3);
            }
            if constexpr (sizeof(OutT) == 2) {
                *reinterpret_cast<__half2*>((__half*)C + (size_t)r0 * N + col)
                    = __floats2half2_rn(v0, v1);
                *reinterpret_cast<__half2*>((__half*)C + (size_t)(r0 + 8) * N + col)
                    = __floats2half2_rn(v2, v3);
            } else {
                *reinterpret_cast<float2*>((float*)C + (size_t)r0 * N + col)
                    = make_float2(v0, v1);
                *reinterpret_cast<float2*>((float*)C + (size_t)(r0 + 8) * N + col)
                    = make_float2(v2, v3);
            }
        }
    }
}

// ---------------- fp32 -> fp16 conversion with optional row padding ----------------
__global__ __launch_bounds__(256) void cvt_f16_pad(
    const float* __restrict__ in, __half* __restrict__ out,
    int kin, int kout, int ncr, int total)
{
    const int idx = blockIdx.x * 256 + threadIdx.x;
    if (idx >= total) return;
    const int r = idx / ncr, c = idx % ncr;
    const float* src = in + (size_t)r * kin + c * 8;
    int valid = kin - c * 8; if (valid > 8) valid = 8;
    __half h[8];
    #pragma unroll
    for (int i = 0; i < 8; i++)
        h[i] = (i < valid) ? __float2half_rn(src[i]) : __ushort_as_half((unsigned short)0);
    *reinterpret_cast<uint4*>(out + (size_t)r * kout + c * 8) = *reinterpret_cast<const uint4*>(h);
}

// ---------------- 2D RoPE + merge transpose, fp16 in/out, fully coalesced ----------------
__global__ __launch_bounds__(256) void rope_merge(
    const __half* __restrict__ pe,
    const float* __restrict__ cosx, const float* __restrict__ sinx,
    const float* __restrict__ cosy, const float* __restrict__ siny,
    __half* __restrict__ A2)
{
    const int wid  = threadIdx.x >> 5;
    const int lane = threadIdx.x & 31;
    const int m = blockIdx.x * 8 + wid;          // 0..8191
    const int b = m >> 10;
    const int rem = m & 1023;
    const int Y = rem >> 5, X = rem & 31;
    const int y0 = 2 * Y, x0 = 2 * X;

    const __half* rows[4];
    #pragma unroll
    for (int p = 0; p < 2; p++)
        #pragma unroll
        for (int q = 0; q < 2; q++)
            rows[p * 2 + q] = pe + ((size_t)(b * 4096 + (y0 + p) * 64 + (x0 + q))) * EMBED;

    __half* dst = A2 + (size_t)m * K2;

    #pragma unroll
    for (int it = 0; it < 8; it++) {
        const int j = it * 32 + lane;            // 4-dim chunk 0..255
        const bool h1 = (j >= 128);              // second half: y-rope
        const int i0 = h1 ? (2 * j - 256) : (2 * j);
        const float* ct = h1 ? cosy : cosx;
        const float* st = h1 ? siny : sinx;

        __half hv[16];                           // index d*4 + pq
        #pragma unroll
        for (int p = 0; p < 2; p++) {
            #pragma unroll
            for (int q = 0; q < 2; q++) {
                const int pos = h1 ? (y0 + p) : (x0 + q);
                const float c0 = ct[pos * 256 + i0],     s0 = st[pos * 256 + i0];
                const float c1 = ct[pos * 256 + i0 + 1], s1 = st[pos * 256 + i0 + 1];
                const uint2 raw = reinterpret_cast<const uint2*>(rows[p * 2 + q])[j];
                const float2 v01 = __half22float2(*reinterpret_cast<const __half2*>(&raw.x));
                const float2 v23 = __half22float2(*reinterpret_cast<const __half2*>(&raw.y));
                const int pq = p * 2 + q;
                hv[0 * 4 + pq] = __float2half_rn(v01.x * c0 - v01.y * s0);
                hv[1 * 4 + pq] = __float2half_rn(v01.x * s0 + v01.y * c0);
                hv[2 * 4 + pq] = __float2half_rn(v23.x * c1 - v23.y * s1);
                hv[3 * 4 + pq] = __float2half_rn(v23.x * s1 + v23.y * c1);
            }
        }
        uint4* d16 = reinterpret_cast<uint4*>(dst + 16 * j);
        d16[0] = reinterpret_cast<const uint4*>(hv)[0];
        d16[1] = reinterpret_cast<const uint4*>(hv)[1];
    }
}

// ---------------- launch ----------------
extern "C" void kernel_launch(void* const* d_in, const int* in_sizes, int n_in,
                              void* d_out, int out_size)
{
    const float* px = (const float*)d_in[0];   // pixel_values [32768, 588]
    const float* pw = (const float*)d_in[2];   // patch_w [1024, 588]
    const float* pb = (const float*)d_in[3];   // patch_b [1024]
    const float* dw = (const float*)d_in[4];   // dense_w [2048, 4096]
    const float* db = (const float*)d_in[5];   // dense_b [2048]
    const float* cx = (const float*)d_in[6];
    const float* sx = (const float*)d_in[7];
    const float* cy = (const float*)d_in[8];
    const float* sy = (const float*)d_in[9];
    float* out = (float*)d_out;                // [8192, 2048]

    __half *peh, *pxh, *w1h, *w2h, *A2h;
    cudaGetSymbolAddress((void**)&peh, g_peh);
    cudaGetSymbolAddress((void**)&pxh, g_pxh);
    cudaGetSymbolAddress((void**)&w1h, g_w1h);
    cudaGetSymbolAddress((void**)&w2h, g_w2h);
    cudaGetSymbolAddress((void**)&A2h, g_A2h);

    const int SMEM = NSTAGE * STAGE_H * sizeof(__half);  // 110592 bytes
    cudaFuncSetAttribute((const void*)hgemm_nt<1, __half>,
                         cudaFuncAttributeMaxDynamicSharedMemorySize, SMEM);
    cudaFuncSetAttribute((const void*)hgemm_nt<0, float>,
                         cudaFuncAttributeMaxDynamicSharedMemorySize, SMEM);

    // Convert operands to fp16 (pixel & patch_w rows padded 588 -> 592)
    {
        int total = N_TOK * (K1P / 8);
        cvt_f16_pad<<<(total + 255) / 256, 256>>>(px, pxh, K1, K1P, K1P / 8, total);
        total = EMBED * (K1P / 8);
        cvt_f16_pad<<<(total + 255) / 256, 256>>>(pw, w1h, K1, K1P, K1P / 8, total);
        total = LLM * (K2 / 8);
        cvt_f16_pad<<<(total + 255) / 256, 256>>>(dw, w2h, K2, K2, K2 / 8, total);
    }

    // Stage 1: pe_h = fp16( gelu(px_h @ pw_h^T + pb) )
    {
        dim3 grid(EMBED / BN, N_TOK / BM);     // (8, 256)
        hgemm_nt<1, __half><<<grid, 256, SMEM>>>(pxh, w1h, pb, peh, N_TOK, EMBED, K1P);
    }

    // Stage 2: RoPE + merge transpose (fp32 math, fp16 io) into A2h
    rope_merge<<<M2 / 8, 256>>>(peh, cx, sx, cy, sy, A2h);

    // Stage 3: out = A2_h @ dw_h^T + db
    {
        dim3 grid(LLM / BN, M2 / BM);          // (16, 64)
        hgemm_nt<0, float><<<grid, 256, SMEM>>>(A2h, w2h, db, out, M2, LLM, K2);
    }
}